// round 2
// baseline (speedup 1.0000x reference)
#include <cuda_runtime.h>
#include <math.h>

// ---------------------------------------------------------------------------
// Scratch (device globals — no allocation allowed)
// ---------------------------------------------------------------------------
// Shapes: BT=8, spatial 32x32=1024, F=128 channels, heads=4, d=32
__device__ float g_bev_feat[8 * 128 * 1024];   // (bt, c, n)
__device__ float g_kv[8 * 192 * 1024];         // (bt, c, n): c<128 hd_feat, c>=128 front
__device__ float g_Q[8 * 4 * 1024 * 32];       // (bt, h, n, d)  (pre-scaled by 1/sqrt(d))
__device__ float g_K[8 * 4 * 1024 * 32];
__device__ float g_V[8 * 4 * 1024 * 32];
__device__ float g_attn[8 * 1024 * 128];       // (bt, n, c) c = h*32+d
__device__ float g_fused[8 * 128 * 1024];      // (bt, c, n)

// ---------------------------------------------------------------------------
// Conv 3x3, SAME padding, stride 1, with optional 16 broadcast "ego" channels
// appended after CIN regular channels. ReLU fused. Output stride configurable.
// grid: (16 oc-groups of 8, 8 bt), block: 256 threads.
// Double-buffered smem over input channels, single __syncthreads per channel.
// ---------------------------------------------------------------------------
template <int CIN, bool EGO>
__global__ __launch_bounds__(256) void conv3x3_relu_kernel(
    const float* __restrict__ in,    // (8, CIN, 32, 32)
    const float* __restrict__ ego,   // (8, 16) or nullptr
    const float* __restrict__ w,     // (128, CTOT, 3, 3)
    const float* __restrict__ bias,  // (128)
    float* __restrict__ out,         // (8, ld_out, 32, 32)
    int ld_out)
{
    constexpr int CTOT = CIN + (EGO ? 16 : 0);
    const int bt  = blockIdx.y;
    const int oc0 = blockIdx.x * 8;
    const int tid = threadIdx.x;
    const int row = tid >> 3;         // 0..31
    const int xq  = (tid & 7) * 4;    // 0,4,...,28

    // padded tile: 34 rows x 34 cols, row stride 35 (conflict-free)
    __shared__ float s_in[2][34 * 35];
    __shared__ float s_w[2][8 * 9];

    float acc[8][4];
#pragma unroll
    for (int j = 0; j < 8; j++) {
        float b = bias[oc0 + j];
#pragma unroll
        for (int p = 0; p < 4; p++) acc[j][p] = b;
    }

    // Precompute staging offsets for the 5 elements this thread stages.
    int soff[5];
    int gidx[5];
    bool inb[5];
#pragma unroll
    for (int k = 0; k < 5; k++) {
        int idx = tid + k * 256;
        bool valid = idx < 34 * 34;
        int y = valid ? (idx / 34 - 1) : 0;
        int x = valid ? (idx % 34 - 1) : 0;
        bool ib = valid && (unsigned)y < 32u && (unsigned)x < 32u;
        soff[k] = valid ? ((y + 1) * 35 + (x + 1)) : 0;
        gidx[k] = y * 32 + x;
        inb[k] = ib;
        if (!valid) soff[k] = -1;
    }
    const int wj = tid / 9, wt = tid - wj * 9;

    float pin[5];
    float pw = 0.f;

    // prefetch ic = 0
    {
        const float* src = in + (bt * CIN + 0) * 1024;
#pragma unroll
        for (int k = 0; k < 5; k++) pin[k] = inb[k] ? src[gidx[k]] : 0.f;
        if (tid < 72) pw = w[((oc0 + wj) * CTOT + 0) * 9 + wt];
    }

    for (int ic = 0; ic < CTOT; ic++) {
        const int b = ic & 1;
        // stage current
#pragma unroll
        for (int k = 0; k < 5; k++)
            if (soff[k] >= 0) s_in[b][soff[k]] = pin[k];
        if (tid < 72) s_w[b][wj * 9 + wt] = pw;

        // prefetch next
        if (ic + 1 < CTOT) {
            int icn = ic + 1;
            if (!EGO || icn < CIN) {
                const float* src = in + (bt * CIN + icn) * 1024;
#pragma unroll
                for (int k = 0; k < 5; k++) pin[k] = inb[k] ? src[gidx[k]] : 0.f;
            } else {
                float ev = ego[bt * 16 + (icn - CIN)];
#pragma unroll
                for (int k = 0; k < 5; k++) pin[k] = inb[k] ? ev : 0.f;
            }
            if (tid < 72) pw = w[((oc0 + wj) * CTOT + icn) * 9 + wt];
        }
        __syncthreads();

        // compute from buffer b
        const float* tile = s_in[b];
        const float* wrow = s_w[b];
#pragma unroll
        for (int ky = 0; ky < 3; ky++) {
            float r[6];
            const float* trow = tile + (row + ky) * 35 + xq;
#pragma unroll
            for (int k = 0; k < 6; k++) r[k] = trow[k];
#pragma unroll
            for (int kx = 0; kx < 3; kx++) {
#pragma unroll
                for (int j = 0; j < 8; j++) {
                    float wv = wrow[j * 9 + ky * 3 + kx];
#pragma unroll
                    for (int p = 0; p < 4; p++)
                        acc[j][p] = fmaf(r[p + kx], wv, acc[j][p]);
                }
            }
        }
        // NOTE: single barrier per iteration is safe with double buffering:
        // a thread staging buffer (b^1) at iter ic+1 has passed sync(ic),
        // which implies every thread finished compute(ic-1) on buffer (b^1).
    }

#pragma unroll
    for (int j = 0; j < 8; j++) {
        float4 v;
        v.x = fmaxf(acc[j][0], 0.f);
        v.y = fmaxf(acc[j][1], 0.f);
        v.z = fmaxf(acc[j][2], 0.f);
        v.w = fmaxf(acc[j][3], 0.f);
        *(float4*)(out + (size_t)(bt * ld_out + oc0 + j) * 1024 + row * 32 + xq) = v;
    }
}

// ---------------------------------------------------------------------------
// Bilinear resize 16x16 -> 32x32 (align_corners=False / half-pixel, edge clamp
// which matches jax.image.resize's renormalized triangle kernel for 2x upsample)
// Writes channels 128..191 of g_kv.
// ---------------------------------------------------------------------------
__global__ __launch_bounds__(256) void resize_front_kernel(
    const float* __restrict__ front)  // (8, 64, 16, 16)
{
    int idx = blockIdx.x * 256 + threadIdx.x;
    if (idx >= 8 * 64 * 1024) return;
    int px = idx & 1023;
    int c  = (idx >> 10) & 63;
    int bt = idx >> 16;
    int y = px >> 5, x = px & 31;

    float sy = y * 0.5f - 0.25f;
    float sx = x * 0.5f - 0.25f;
    int y0 = __float2int_rd(sy);
    int x0 = __float2int_rd(sx);
    float fy = sy - (float)y0;
    float fx = sx - (float)x0;
    int y0c = max(y0, 0), y1c = min(y0 + 1, 15);
    int x0c = max(x0, 0), x1c = min(x0 + 1, 15);

    const float* src = front + (bt * 64 + c) * 256;
    float a = src[y0c * 16 + x0c];
    float b = src[y0c * 16 + x1c];
    float cc = src[y1c * 16 + x0c];
    float d = src[y1c * 16 + x1c];
    float top = a + fx * (b - a);
    float bot = cc + fx * (d - cc);
    g_kv[(size_t)(bt * 192 + 128 + c) * 1024 + px] = top + fy * (bot - top);
}

// ---------------------------------------------------------------------------
// Projection: out[bt,h,n,d] = scale * sum_c X[bt,c,n] * W[h*32+d, c]
// grid: (16 n-tiles of 64, 8 bt), block 256. Tile 64n x 128o, K-chunks of 16.
// ---------------------------------------------------------------------------
__global__ __launch_bounds__(256) void proj_qkv_kernel(
    const float* __restrict__ X,   // (8, C, 1024)
    const float* __restrict__ W,   // (128, C)
    float* __restrict__ out,       // (8, 4, 1024, 32)
    int C, float scale)
{
    const int bt = blockIdx.y;
    const int n0 = blockIdx.x * 64;
    const int tid = threadIdx.x;
    const int tn = tid & 15;
    const int to = tid >> 4;

    __shared__ float sX[16][68];
    __shared__ float sW[16][132];

    float acc[4][8];
#pragma unroll
    for (int i = 0; i < 4; i++)
#pragma unroll
        for (int j = 0; j < 8; j++) acc[i][j] = 0.f;

    const int lc = tid >> 4;
    const int ln = (tid & 15) * 4;
    const int lo = tid & 127;
    const int lwc = (tid >> 7) * 8;

    for (int c0 = 0; c0 < C; c0 += 16) {
        float4 xv = *(const float4*)&X[(size_t)(bt * C + c0 + lc) * 1024 + n0 + ln];
        sX[lc][ln + 0] = xv.x; sX[lc][ln + 1] = xv.y;
        sX[lc][ln + 2] = xv.z; sX[lc][ln + 3] = xv.w;
#pragma unroll
        for (int k = 0; k < 8; k++) sW[lwc + k][lo] = W[lo * C + c0 + lwc + k];
        __syncthreads();
#pragma unroll
        for (int c = 0; c < 16; c++) {
            float xr[4], wr[8];
#pragma unroll
            for (int i = 0; i < 4; i++) xr[i] = sX[c][tn * 4 + i];
#pragma unroll
            for (int j = 0; j < 8; j++) wr[j] = sW[c][to * 8 + j];
#pragma unroll
            for (int i = 0; i < 4; i++)
#pragma unroll
                for (int j = 0; j < 8; j++)
                    acc[i][j] = fmaf(xr[i], wr[j], acc[i][j]);
        }
        __syncthreads();
    }

#pragma unroll
    for (int i = 0; i < 4; i++) {
        int n = n0 + tn * 4 + i;
#pragma unroll
        for (int j = 0; j < 8; j++) {
            int o = to * 8 + j;
            out[(size_t)bt * 131072 + (o >> 5) * 32768 + n * 32 + (o & 31)] =
                acc[i][j] * scale;
        }
    }
}

// ---------------------------------------------------------------------------
// Attention: one thread = one query (online softmax), K/V tiles staged in smem.
// grid: (8 q-tiles of 128, 4 heads, 8 bt), block 128.
// Q was pre-scaled by 1/sqrt(32) in its projection.
// ---------------------------------------------------------------------------
__global__ __launch_bounds__(128) void attention_kernel()
{
    const int q0 = blockIdx.x * 128;
    const int h  = blockIdx.y;
    const int bt = blockIdx.z;
    const int tid = threadIdx.x;
    const int n = q0 + tid;
    const size_t base = (size_t)(bt * 4 + h) * 1024 * 32;

    float q[32];
    {
        const float4* qp = (const float4*)(g_Q + base + (size_t)n * 32);
#pragma unroll
        for (int i = 0; i < 8; i++) {
            float4 v = qp[i];
            q[4 * i] = v.x; q[4 * i + 1] = v.y; q[4 * i + 2] = v.z; q[4 * i + 3] = v.w;
        }
    }
    float m = -1e30f, l = 0.f;
    float acc[32];
#pragma unroll
    for (int i = 0; i < 32; i++) acc[i] = 0.f;

    __shared__ float4 sK[128 * 8];
    __shared__ float4 sV[128 * 8];

    for (int kt = 0; kt < 8; kt++) {
        const float4* kp = (const float4*)(g_K + base + (size_t)kt * 128 * 32);
        const float4* vp = (const float4*)(g_V + base + (size_t)kt * 128 * 32);
#pragma unroll
        for (int r = 0; r < 8; r++) {
            sK[tid + r * 128] = kp[tid + r * 128];
            sV[tid + r * 128] = vp[tid + r * 128];
        }
        __syncthreads();

        for (int j = 0; j < 128; j++) {
            const float4* krow = sK + j * 8;
            float s0 = 0.f, s1 = 0.f, s2 = 0.f, s3 = 0.f;
#pragma unroll
            for (int i = 0; i < 8; i++) {
                float4 kv4 = krow[i];
                s0 = fmaf(q[4 * i],     kv4.x, s0);
                s1 = fmaf(q[4 * i + 1], kv4.y, s1);
                s2 = fmaf(q[4 * i + 2], kv4.z, s2);
                s3 = fmaf(q[4 * i + 3], kv4.w, s3);
            }
            float s = (s0 + s1) + (s2 + s3);
            const float4* vrow = sV + j * 8;
            if (s > m) {
                float corr = __expf(m - s);
                l = l * corr + 1.f;
                m = s;
#pragma unroll
                for (int i = 0; i < 8; i++) {
                    float4 vv = vrow[i];
                    acc[4 * i]     = fmaf(acc[4 * i],     corr, vv.x);
                    acc[4 * i + 1] = fmaf(acc[4 * i + 1], corr, vv.y);
                    acc[4 * i + 2] = fmaf(acc[4 * i + 2], corr, vv.z);
                    acc[4 * i + 3] = fmaf(acc[4 * i + 3], corr, vv.w);
                }
            } else {
                float p = __expf(s - m);
                l += p;
#pragma unroll
                for (int i = 0; i < 8; i++) {
                    float4 vv = vrow[i];
                    acc[4 * i]     = fmaf(p, vv.x, acc[4 * i]);
                    acc[4 * i + 1] = fmaf(p, vv.y, acc[4 * i + 1]);
                    acc[4 * i + 2] = fmaf(p, vv.z, acc[4 * i + 2]);
                    acc[4 * i + 3] = fmaf(p, vv.w, acc[4 * i + 3]);
                }
            }
        }
        __syncthreads();
    }

    float inv = 1.f / l;
    float4* op = (float4*)(g_attn + (size_t)(bt * 1024 + n) * 128 + h * 32);
#pragma unroll
    for (int i = 0; i < 8; i++) {
        float4 v;
        v.x = acc[4 * i] * inv;
        v.y = acc[4 * i + 1] * inv;
        v.z = acc[4 * i + 2] * inv;
        v.w = acc[4 * i + 3] * inv;
        op[i] = v;
    }
}

// ---------------------------------------------------------------------------
// Output projection: g_fused[bt,o,n] = sum_c g_attn[bt,n,c] * wo[o,c] + bo[o]
// ---------------------------------------------------------------------------
__global__ __launch_bounds__(256) void proj_out_kernel(
    const float* __restrict__ W,    // (128, 128) wo
    const float* __restrict__ bias) // (128) bo
{
    const int bt = blockIdx.y;
    const int n0 = blockIdx.x * 64;
    const int tid = threadIdx.x;
    const int tn = tid & 15;
    const int to = tid >> 4;

    __shared__ float sX[16][68];
    __shared__ float sW[16][132];

    float acc[4][8];
#pragma unroll
    for (int j = 0; j < 8; j++) {
        float b = bias[to * 8 + j];
#pragma unroll
        for (int i = 0; i < 4; i++) acc[i][j] = b;
    }

    const int ln = tid & 63;
    const int lcc = (tid >> 6) * 4;
    const int lo = tid & 127;
    const int lwc = (tid >> 7) * 8;

    for (int c0 = 0; c0 < 128; c0 += 16) {
        float4 av = *(const float4*)&g_attn[(size_t)(bt * 1024 + n0 + ln) * 128 + c0 + lcc];
        sX[lcc + 0][ln] = av.x; sX[lcc + 1][ln] = av.y;
        sX[lcc + 2][ln] = av.z; sX[lcc + 3][ln] = av.w;
#pragma unroll
        for (int k = 0; k < 8; k++) sW[lwc + k][lo] = W[lo * 128 + c0 + lwc + k];
        __syncthreads();
#pragma unroll
        for (int c = 0; c < 16; c++) {
            float xr[4], wr[8];
#pragma unroll
            for (int i = 0; i < 4; i++) xr[i] = sX[c][tn * 4 + i];
#pragma unroll
            for (int j = 0; j < 8; j++) wr[j] = sW[c][to * 8 + j];
#pragma unroll
            for (int i = 0; i < 4; i++)
#pragma unroll
                for (int j = 0; j < 8; j++)
                    acc[i][j] = fmaf(xr[i], wr[j], acc[i][j]);
        }
        __syncthreads();
    }

#pragma unroll
    for (int j = 0; j < 8; j++) {
        int o = to * 8 + j;
#pragma unroll
        for (int i = 0; i < 4; i++) {
            int n = n0 + tn * 4 + i;
            g_fused[(size_t)(bt * 128 + o) * 1024 + n] = acc[i][j];
        }
    }
}

// ---------------------------------------------------------------------------
// Launch
// ---------------------------------------------------------------------------
extern "C" void kernel_launch(void* const* d_in, const int* in_sizes, int n_in,
                              void* d_out, int out_size)
{
    const float* bev   = (const float*)d_in[0];
    const float* hd    = (const float*)d_in[1];
    const float* ego   = (const float*)d_in[2];
    const float* front = (const float*)d_in[3];
    const float* w_bev = (const float*)d_in[4];
    const float* b_bev = (const float*)d_in[5];
    const float* w_hd  = (const float*)d_in[6];
    const float* b_hd  = (const float*)d_in[7];
    const float* wq    = (const float*)d_in[8];
    const float* wk    = (const float*)d_in[9];
    const float* wv    = (const float*)d_in[10];
    const float* wo    = (const float*)d_in[11];
    const float* bo    = (const float*)d_in[12];
    const float* w_out = (const float*)d_in[13];
    const float* b_out = (const float*)d_in[14];
    float* out = (float*)d_out;

    float *p_bev_feat, *p_kv, *p_fused, *p_Q, *p_K, *p_V;
    cudaGetSymbolAddress((void**)&p_bev_feat, g_bev_feat);
    cudaGetSymbolAddress((void**)&p_kv, g_kv);
    cudaGetSymbolAddress((void**)&p_fused, g_fused);
    cudaGetSymbolAddress((void**)&p_Q, g_Q);
    cudaGetSymbolAddress((void**)&p_K, g_K);
    cudaGetSymbolAddress((void**)&p_V, g_V);

    const float scale = 0.17677669529663687f;  // 32^-0.5

    // Stage 1: input convs + front resize
    conv3x3_relu_kernel<128, true><<<dim3(16, 8), 256>>>(
        bev, ego, w_bev, b_bev, p_bev_feat, 128);
    conv3x3_relu_kernel<64, false><<<dim3(16, 8), 256>>>(
        hd, nullptr, w_hd, b_hd, p_kv, 192);
    resize_front_kernel<<<2048, 256>>>(front);

    // Stage 2: projections (Q pre-scaled)
    proj_qkv_kernel<<<dim3(16, 8), 256>>>(p_bev_feat, wq, p_Q, 128, scale);
    proj_qkv_kernel<<<dim3(16, 8), 256>>>(p_kv, wk, p_K, 192, 1.0f);
    proj_qkv_kernel<<<dim3(16, 8), 256>>>(p_kv, wv, p_V, 192, 1.0f);

    // Stage 3: attention
    attention_kernel<<<dim3(8, 4, 8), 128>>>();

    // Stage 4: output projection
    proj_out_kernel<<<dim3(16, 8), 256>>>(wo, bo);

    // Stage 5: final conv (reads g_fused + ego, writes d_out)
    conv3x3_relu_kernel<128, true><<<dim3(16, 8), 256>>>(
        p_fused, ego, w_out, b_out, out, 128);
}

// round 3
// speedup vs baseline: 2.8436x; 2.8436x over previous
#include <cuda_runtime.h>
#include <stdint.h>

// ---------------------------------------------------------------------------
// Scratch
// ---------------------------------------------------------------------------
__device__ float g_bev_feat[8 * 128 * 1024];   // (bt, c, n)
__device__ float g_kv[8 * 192 * 1024];         // (bt, c, n)
__device__ float g_Q[8 * 4 * 1024 * 32];       // (bt,h,n,d) scaled by 1/sqrt(d)*log2e
__device__ float g_K[8 * 4 * 1024 * 32];
__device__ float g_V[8 * 4 * 1024 * 32];
__device__ float g_attn[8 * 1024 * 128];       // (bt, n, c)
__device__ float g_fused[8 * 128 * 1024];      // (bt, c, n)
__device__ float g_ego[8 * 16 * 1024];         // ego broadcast spatially

// ---------------------------------------------------------------------------
// Helpers
// ---------------------------------------------------------------------------
__device__ __forceinline__ float f2tf(float x) {
    uint32_t u;
    asm("cvt.rna.tf32.f32 %0,%1;" : "=r"(u) : "f"(x));
    return __uint_as_float(u);
}
__device__ __forceinline__ float ex2f(float x) {
    float y;
    asm("ex2.approx.f32 %0,%1;" : "=f"(y) : "f"(x));
    return y;
}
__device__ __forceinline__ void mma8(float* c, float a0, float a1, float a2,
                                     float a3, float b0, float b1) {
    asm("mma.sync.aligned.m16n8k8.row.col.f32.tf32.tf32.f32 "
        "{%0,%1,%2,%3},{%4,%5,%6,%7},{%8,%9},{%0,%1,%2,%3};"
        : "+f"(c[0]), "+f"(c[1]), "+f"(c[2]), "+f"(c[3])
        : "r"(__float_as_uint(a0)), "r"(__float_as_uint(a1)),
          "r"(__float_as_uint(a2)), "r"(__float_as_uint(a3)),
          "r"(__float_as_uint(b0)), "r"(__float_as_uint(b1)));
}

// ---------------------------------------------------------------------------
// Elementwise prep
// ---------------------------------------------------------------------------
__global__ __launch_bounds__(256) void ego_spread_kernel(const float* __restrict__ ego) {
    int idx = blockIdx.x * 256 + threadIdx.x;
    if (idx >= 8 * 16 * 1024) return;
    int bt = idx >> 14, e = (idx >> 10) & 15;
    g_ego[idx] = ego[bt * 16 + e];
}

__global__ __launch_bounds__(256) void resize_front_kernel(const float* __restrict__ front) {
    int idx = blockIdx.x * 256 + threadIdx.x;
    if (idx >= 8 * 64 * 1024) return;
    int px = idx & 1023, c = (idx >> 10) & 63, bt = idx >> 16;
    int y = px >> 5, x = px & 31;
    float sy = y * 0.5f - 0.25f, sx = x * 0.5f - 0.25f;
    int y0 = __float2int_rd(sy), x0 = __float2int_rd(sx);
    float fy = sy - y0, fx = sx - x0;
    int y0c = max(y0, 0), y1c = min(y0 + 1, 15);
    int x0c = max(x0, 0), x1c = min(x0 + 1, 15);
    const float* src = front + (bt * 64 + c) * 256;
    float a = src[y0c * 16 + x0c], b = src[y0c * 16 + x1c];
    float cc = src[y1c * 16 + x0c], d = src[y1c * 16 + x1c];
    float top = a + fx * (b - a), bot = cc + fx * (d - cc);
    g_kv[(size_t)(bt * 192 + 128 + c) * 1024 + px] = top + fy * (bot - top);
}

// ---------------------------------------------------------------------------
// Conv 3x3 SAME via implicit GEMM on tf32 mma. Block: 32oc x 256px, 8 warps.
// grid (4 ocg, 4 rowg, 8 bt).
// ---------------------------------------------------------------------------
template <int CIN, bool EGO>
__global__ __launch_bounds__(256) void conv_mma_kernel(
    const float* __restrict__ in, const float* __restrict__ w,
    const float* __restrict__ bias, float* __restrict__ out, int ld_out) {
    constexpr int CTOT = CIN + (EGO ? 16 : 0);
    constexpr int NCH = CTOT / 8;
    const int oc_base = blockIdx.x * 32;
    const int y0 = blockIdx.y * 8;
    const int bt = blockIdx.z;
    const int tid = threadIdx.x;
    const int warp = tid >> 5, lane = tid & 31;
    const int g = lane >> 2, t4 = lane & 3;
    const int om = warp >> 2, pw = warp & 3;

    __shared__ __align__(16) float s_in[8 * 344];   // 8 ic x (10x34), stride 344
    __shared__ __align__(16) float s_w[32 * 76];    // 32 oc x 72k, stride 76

    // staging map: 2720 input elems over 256 threads (11 slots)
    int sdst[11], ssrc[11];
    unsigned vmask = 0, amask = 0;
#pragma unroll
    for (int s = 0; s < 11; s++) {
        int idx = tid + s * 256;
        sdst[s] = 0; ssrc[s] = 0;
        if (idx < 2720) {
            amask |= 1u << s;
            int icl = idx / 340, rem = idx - icl * 340;
            int rr = rem / 34, cc = rem - rr * 34;
            int Y = y0 - 1 + rr, X = cc - 1;
            sdst[s] = icl * 344 + rem;
            if ((unsigned)Y < 32u && (unsigned)X < 32u) {
                vmask |= 1u << s;
                ssrc[s] = icl * 1024 + Y * 32 + X;
            }
        }
    }
    const int woc = tid >> 3, wicl = tid & 7;

    float C[8][4];
#pragma unroll
    for (int nt = 0; nt < 8; nt++)
#pragma unroll
        for (int i = 0; i < 4; i++) C[nt][i] = 0.f;

    float pin[11], pwv[9];
    // prefetch chunk 0
    {
        const float* src = (EGO && 0 >= CIN) ? nullptr : in + (size_t)bt * CIN * 1024;
#pragma unroll
        for (int s = 0; s < 11; s++)
            pin[s] = (vmask >> s & 1) ? __ldg(src + ssrc[s]) : 0.f;
        const float* wp = w + ((size_t)(oc_base + woc) * CTOT + wicl) * 9;
#pragma unroll
        for (int j = 0; j < 9; j++) pwv[j] = __ldg(wp + j);
    }

    for (int ch = 0; ch < NCH; ch++) {
        // store staged chunk
#pragma unroll
        for (int s = 0; s < 11; s++)
            if (amask >> s & 1) s_in[sdst[s]] = f2tf(pin[s]);
#pragma unroll
        for (int j = 0; j < 9; j++) s_w[woc * 76 + j * 8 + wicl] = f2tf(pwv[j]);
        __syncthreads();

        // prefetch next chunk
        if (ch + 1 < NCH) {
            int ic0 = (ch + 1) * 8;
            const float* src = (EGO && ic0 >= CIN)
                                   ? g_ego + bt * 16384 + (ic0 - CIN) * 1024
                                   : in + (size_t)bt * CIN * 1024 + ic0 * 1024;
#pragma unroll
            for (int s = 0; s < 11; s++)
                pin[s] = (vmask >> s & 1) ? __ldg(src + ssrc[s]) : 0.f;
            const float* wp = w + ((size_t)(oc_base + woc) * CTOT + ic0 + wicl) * 9;
#pragma unroll
            for (int j = 0; j < 9; j++) pwv[j] = __ldg(wp + j);
        }

#pragma unroll
        for (int kt = 0; kt < 9; kt++) {
            const int dy = kt / 3, dx = kt % 3;
            float a0 = s_w[(om * 16 + g) * 76 + kt * 8 + t4];
            float a1 = s_w[(om * 16 + g + 8) * 76 + kt * 8 + t4];
            float a2 = s_w[(om * 16 + g) * 76 + kt * 8 + t4 + 4];
            float a3 = s_w[(om * 16 + g + 8) * 76 + kt * 8 + t4 + 4];
#pragma unroll
            for (int nt = 0; nt < 8; nt++) {
                int base = (2 * pw + (nt >> 2) + dy) * 34 + (nt & 3) * 8 + g + dx;
                float b0 = s_in[t4 * 344 + base];
                float b1 = s_in[(t4 + 4) * 344 + base];
                mma8(C[nt], a0, a1, a2, a3, b0, b1);
            }
        }
        __syncthreads();
    }

    const int o0 = oc_base + om * 16 + g, o1 = o0 + 8;
    const float bv0 = bias[o0], bv1 = bias[o1];
#pragma unroll
    for (int nt = 0; nt < 8; nt++) {
        int y = y0 + 2 * pw + (nt >> 2);
        int x = (nt & 3) * 8 + 2 * t4;
        int px = y * 32 + x;
        float2 v0 = {fmaxf(C[nt][0] + bv0, 0.f), fmaxf(C[nt][1] + bv0, 0.f)};
        float2 v1 = {fmaxf(C[nt][2] + bv1, 0.f), fmaxf(C[nt][3] + bv1, 0.f)};
        *(float2*)(out + (size_t)(bt * ld_out + o0) * 1024 + px) = v0;
        *(float2*)(out + (size_t)(bt * ld_out + o1) * 1024 + px) = v1;
    }
}

// ---------------------------------------------------------------------------
// QKV projection: out(bt,h,n,d) = scale * W(128,C) @ X(bt,C,1024).
// Block 128o x 128n, 8 warps (4m x 2n). grid (8 ng, 8 bt).
// ---------------------------------------------------------------------------
__global__ __launch_bounds__(256) void proj_qkv_mma(
    const float* __restrict__ X, const float* __restrict__ W,
    float* __restrict__ out, int Cdim, float scale) {
    const int n0 = blockIdx.x * 128;
    const int bt = blockIdx.y;
    const int tid = threadIdx.x;
    const int warp = tid >> 5, lane = tid & 31;
    const int g = lane >> 2, t4 = lane & 3;
    const int om = warp >> 1, nw = warp & 1;

    __shared__ __align__(16) float sX[8 * 136];
    __shared__ __align__(16) float sW[128 * 12];

    float C[2][8][4];
#pragma unroll
    for (int mi = 0; mi < 2; mi++)
#pragma unroll
        for (int nt = 0; nt < 8; nt++)
#pragma unroll
            for (int i = 0; i < 4; i++) C[mi][nt][i] = 0.f;

    const int xk = tid >> 5, xn = lane * 4;
    const int wo = tid & 127, wk = (tid >> 7) * 4;

    float4 px4 = *(const float4*)(X + (size_t)(bt * Cdim + xk) * 1024 + n0 + xn);
    float4 pw4 = *(const float4*)(W + (size_t)wo * Cdim + wk);

    const int NK = Cdim / 8;
    for (int ck = 0; ck < NK; ck++) {
        sX[xk * 136 + xn + 0] = f2tf(px4.x);
        sX[xk * 136 + xn + 1] = f2tf(px4.y);
        sX[xk * 136 + xn + 2] = f2tf(px4.z);
        sX[xk * 136 + xn + 3] = f2tf(px4.w);
        sW[wo * 12 + wk + 0] = f2tf(pw4.x);
        sW[wo * 12 + wk + 1] = f2tf(pw4.y);
        sW[wo * 12 + wk + 2] = f2tf(pw4.z);
        sW[wo * 12 + wk + 3] = f2tf(pw4.w);
        __syncthreads();
        if (ck + 1 < NK) {
            int c0 = (ck + 1) * 8;
            px4 = *(const float4*)(X + (size_t)(bt * Cdim + c0 + xk) * 1024 + n0 + xn);
            pw4 = *(const float4*)(W + (size_t)wo * Cdim + c0 + wk);
        }
#pragma unroll
        for (int mi = 0; mi < 2; mi++) {
            int ob = (om * 32 + mi * 16 + g) * 12;
            float a0 = sW[ob + t4];
            float a1 = sW[ob + 96 + t4];
            float a2 = sW[ob + t4 + 4];
            float a3 = sW[ob + 96 + t4 + 4];
#pragma unroll
            for (int nt = 0; nt < 8; nt++) {
                float b0 = sX[t4 * 136 + nw * 64 + nt * 8 + g];
                float b1 = sX[(t4 + 4) * 136 + nw * 64 + nt * 8 + g];
                mma8(C[mi][nt], a0, a1, a2, a3, b0, b1);
            }
        }
        __syncthreads();
    }

#pragma unroll
    for (int mi = 0; mi < 2; mi++) {
        int o0 = om * 32 + mi * 16 + g, o1 = o0 + 8;
        size_t b0 = (size_t)(bt * 4 + (o0 >> 5)) * 32768 + (o0 & 31);
        size_t b1 = (size_t)(bt * 4 + (o1 >> 5)) * 32768 + (o1 & 31);
#pragma unroll
        for (int nt = 0; nt < 8; nt++) {
            int n = n0 + nw * 64 + nt * 8 + 2 * t4;
            out[b0 + (size_t)n * 32] = C[mi][nt][0] * scale;
            out[b0 + (size_t)(n + 1) * 32] = C[mi][nt][1] * scale;
            out[b1 + (size_t)n * 32] = C[mi][nt][2] * scale;
            out[b1 + (size_t)(n + 1) * 32] = C[mi][nt][3] * scale;
        }
    }
}

// ---------------------------------------------------------------------------
// Output projection: g_fused(bt,o,n) = wo(128,128) @ g_attn(bt,n,128)^T + bo
// ---------------------------------------------------------------------------
__global__ __launch_bounds__(256) void proj_out_mma(
    const float* __restrict__ W, const float* __restrict__ bias) {
    const int n0 = blockIdx.x * 128;
    const int bt = blockIdx.y;
    const int tid = threadIdx.x;
    const int warp = tid >> 5, lane = tid & 31;
    const int g = lane >> 2, t4 = lane & 3;
    const int om = warp >> 1, nw = warp & 1;

    __shared__ __align__(16) float sX[8 * 136];
    __shared__ __align__(16) float sW[128 * 12];

    float C[2][8][4];
#pragma unroll
    for (int mi = 0; mi < 2; mi++)
#pragma unroll
        for (int nt = 0; nt < 8; nt++)
#pragma unroll
            for (int i = 0; i < 4; i++) C[mi][nt][i] = 0.f;

    const int xn = tid & 127, xc = (tid >> 7) * 4;
    const int wo2 = tid & 127, wk = (tid >> 7) * 4;

    float4 px4 = *(const float4*)(g_attn + (size_t)(bt * 1024 + n0 + xn) * 128 + xc);
    float4 pw4 = *(const float4*)(W + (size_t)wo2 * 128 + wk);

    for (int ck = 0; ck < 16; ck++) {
        sX[(xc + 0) * 136 + xn] = f2tf(px4.x);
        sX[(xc + 1) * 136 + xn] = f2tf(px4.y);
        sX[(xc + 2) * 136 + xn] = f2tf(px4.z);
        sX[(xc + 3) * 136 + xn] = f2tf(px4.w);
        sW[wo2 * 12 + wk + 0] = f2tf(pw4.x);
        sW[wo2 * 12 + wk + 1] = f2tf(pw4.y);
        sW[wo2 * 12 + wk + 2] = f2tf(pw4.z);
        sW[wo2 * 12 + wk + 3] = f2tf(pw4.w);
        __syncthreads();
        if (ck + 1 < 16) {
            int c0 = (ck + 1) * 8;
            px4 = *(const float4*)(g_attn + (size_t)(bt * 1024 + n0 + xn) * 128 + c0 + xc);
            pw4 = *(const float4*)(W + (size_t)wo2 * 128 + c0 + wk);
        }
#pragma unroll
        for (int mi = 0; mi < 2; mi++) {
            int ob = (om * 32 + mi * 16 + g) * 12;
            float a0 = sW[ob + t4];
            float a1 = sW[ob + 96 + t4];
            float a2 = sW[ob + t4 + 4];
            float a3 = sW[ob + 96 + t4 + 4];
#pragma unroll
            for (int nt = 0; nt < 8; nt++) {
                float b0 = sX[t4 * 136 + nw * 64 + nt * 8 + g];
                float b1 = sX[(t4 + 4) * 136 + nw * 64 + nt * 8 + g];
                mma8(C[mi][nt], a0, a1, a2, a3, b0, b1);
            }
        }
        __syncthreads();
    }

#pragma unroll
    for (int mi = 0; mi < 2; mi++) {
        int o0 = om * 32 + mi * 16 + g, o1 = o0 + 8;
        float bv0 = bias[o0], bv1 = bias[o1];
#pragma unroll
        for (int nt = 0; nt < 8; nt++) {
            int n = n0 + nw * 64 + nt * 8 + 2 * t4;
            float2 v0 = {C[mi][nt][0] + bv0, C[mi][nt][1] + bv0};
            float2 v1 = {C[mi][nt][2] + bv1, C[mi][nt][3] + bv1};
            *(float2*)(g_fused + (size_t)(bt * 128 + o0) * 1024 + n) = v0;
            *(float2*)(g_fused + (size_t)(bt * 128 + o1) * 1024 + n) = v1;
        }
    }
}

// ---------------------------------------------------------------------------
// Flash attention on tf32 mma. Block: 128 q (8 warps x 16q), loops 8 key-tiles
// of 128. V staged with row-permutation so S's C-fragment feeds PV's A-fragment.
// Q pre-scaled by 1/sqrt(d)*log2e; softmax via ex2.
// ---------------------------------------------------------------------------
__global__ __launch_bounds__(256) void attn_mma_kernel() {
    const int q0 = blockIdx.x * 128;
    const int h = blockIdx.y;
    const int bt = blockIdx.z;
    const int tid = threadIdx.x;
    const int warp = tid >> 5, lane = tid & 31;
    const int g = lane >> 2, t4 = lane & 3;
    const size_t hb = (size_t)(bt * 4 + h) * 32768;

    __shared__ __align__(16) float sK[128 * 36];
    __shared__ __align__(16) float sV[128 * 36];

    // Q fragments (persist across key tiles)
    float qa[4][4];
    {
        const float* qp = g_Q + hb + (size_t)(q0 + warp * 16) * 32;
#pragma unroll
        for (int dc = 0; dc < 4; dc++) {
            qa[dc][0] = f2tf(qp[g * 32 + dc * 8 + t4]);
            qa[dc][1] = f2tf(qp[(g + 8) * 32 + dc * 8 + t4]);
            qa[dc][2] = f2tf(qp[g * 32 + dc * 8 + t4 + 4]);
            qa[dc][3] = f2tf(qp[(g + 8) * 32 + dc * 8 + t4 + 4]);
        }
    }

    float O[4][4];
#pragma unroll
    for (int dt = 0; dt < 4; dt++)
#pragma unroll
        for (int i = 0; i < 4; i++) O[dt][i] = 0.f;
    float m0 = -1e30f, m1 = -1e30f, l0 = 0.f, l1 = 0.f;

    const int key = tid >> 1, dg = (tid & 1) * 16;
    const int klo = key & 7;
    const int prow = (key & ~7) | ((klo >> 1) | ((klo & 1) << 2));

    for (int kt = 0; kt < 8; kt++) {
        const float* kp = g_K + hb + (size_t)(kt * 128 + key) * 32 + dg;
        const float* vp = g_V + hb + (size_t)(kt * 128 + key) * 32 + dg;
#pragma unroll
        for (int j = 0; j < 4; j++) {
            float4 kv = *(const float4*)(kp + 4 * j);
            float4 vv = *(const float4*)(vp + 4 * j);
            float4 kr = {f2tf(kv.x), f2tf(kv.y), f2tf(kv.z), f2tf(kv.w)};
            float4 vr = {f2tf(vv.x), f2tf(vv.y), f2tf(vv.z), f2tf(vv.w)};
            *(float4*)&sK[key * 36 + dg + 4 * j] = kr;
            *(float4*)&sV[prow * 36 + dg + 4 * j] = vr;
        }
        __syncthreads();

        float S[16][4];
#pragma unroll
        for (int nt = 0; nt < 16; nt++) {
#pragma unroll
            for (int i = 0; i < 4; i++) S[nt][i] = 0.f;
#pragma unroll
            for (int dc = 0; dc < 4; dc++) {
                float b0 = sK[(nt * 8 + g) * 36 + dc * 8 + t4];
                float b1 = sK[(nt * 8 + g) * 36 + dc * 8 + t4 + 4];
                mma8(S[nt], qa[dc][0], qa[dc][1], qa[dc][2], qa[dc][3], b0, b1);
            }
        }

        // online softmax (log2 domain)
        float mx0 = -1e30f, mx1 = -1e30f;
#pragma unroll
        for (int nt = 0; nt < 16; nt++) {
            mx0 = fmaxf(mx0, fmaxf(S[nt][0], S[nt][1]));
            mx1 = fmaxf(mx1, fmaxf(S[nt][2], S[nt][3]));
        }
        mx0 = fmaxf(mx0, __shfl_xor_sync(0xffffffff, mx0, 1));
        mx0 = fmaxf(mx0, __shfl_xor_sync(0xffffffff, mx0, 2));
        mx1 = fmaxf(mx1, __shfl_xor_sync(0xffffffff, mx1, 1));
        mx1 = fmaxf(mx1, __shfl_xor_sync(0xffffffff, mx1, 2));
        float mn0 = fmaxf(m0, mx0), mn1 = fmaxf(m1, mx1);
        float sc0 = ex2f(m0 - mn0), sc1 = ex2f(m1 - mn1);
        m0 = mn0; m1 = mn1;

        float ls0 = 0.f, ls1 = 0.f;
#pragma unroll
        for (int nt = 0; nt < 16; nt++) {
            S[nt][0] = f2tf(ex2f(S[nt][0] - mn0));
            S[nt][1] = f2tf(ex2f(S[nt][1] - mn0));
            S[nt][2] = f2tf(ex2f(S[nt][2] - mn1));
            S[nt][3] = f2tf(ex2f(S[nt][3] - mn1));
            ls0 += S[nt][0] + S[nt][1];
            ls1 += S[nt][2] + S[nt][3];
        }
        ls0 += __shfl_xor_sync(0xffffffff, ls0, 1);
        ls0 += __shfl_xor_sync(0xffffffff, ls0, 2);
        ls1 += __shfl_xor_sync(0xffffffff, ls1, 1);
        ls1 += __shfl_xor_sync(0xffffffff, ls1, 2);
        l0 = l0 * sc0 + ls0;
        l1 = l1 * sc1 + ls1;

#pragma unroll
        for (int dt = 0; dt < 4; dt++) {
            O[dt][0] *= sc0; O[dt][1] *= sc0;
            O[dt][2] *= sc1; O[dt][3] *= sc1;
        }

        // PV: S C-frag (c0,c2,c1,c3) is the A-frag under V row-permutation
#pragma unroll
        for (int kc = 0; kc < 16; kc++) {
            float a0 = S[kc][0], a1 = S[kc][2], a2 = S[kc][1], a3 = S[kc][3];
#pragma unroll
            for (int dt = 0; dt < 4; dt++) {
                float b0 = sV[(kc * 8 + t4) * 36 + dt * 8 + g];
                float b1 = sV[(kc * 8 + t4 + 4) * 36 + dt * 8 + g];
                mma8(O[dt], a0, a1, a2, a3, b0, b1);
            }
        }
        __syncthreads();
    }

    float inv0 = 1.f / l0, inv1 = 1.f / l1;
    int q = q0 + warp * 16 + g;
    size_t ob = (size_t)(bt * 1024 + q) * 128 + h * 32;
#pragma unroll
    for (int dt = 0; dt < 4; dt++) {
        float2 v0 = {O[dt][0] * inv0, O[dt][1] * inv0};
        float2 v1 = {O[dt][2] * inv1, O[dt][3] * inv1};
        *(float2*)(g_attn + ob + dt * 8 + 2 * t4) = v0;
        *(float2*)(g_attn + ob + 8 * 128 + dt * 8 + 2 * t4) = v1;
    }
}

// ---------------------------------------------------------------------------
// Launch
// ---------------------------------------------------------------------------
extern "C" void kernel_launch(void* const* d_in, const int* in_sizes, int n_in,
                              void* d_out, int out_size) {
    const float* bev   = (const float*)d_in[0];
    const float* hd    = (const float*)d_in[1];
    const float* ego   = (const float*)d_in[2];
    const float* front = (const float*)d_in[3];
    const float* w_bev = (const float*)d_in[4];
    const float* b_bev = (const float*)d_in[5];
    const float* w_hd  = (const float*)d_in[6];
    const float* b_hd  = (const float*)d_in[7];
    const float* wq    = (const float*)d_in[8];
    const float* wk    = (const float*)d_in[9];
    const float* wv    = (const float*)d_in[10];
    const float* wo    = (const float*)d_in[11];
    const float* bo    = (const float*)d_in[12];
    const float* w_out = (const float*)d_in[13];
    const float* b_out = (const float*)d_in[14];
    float* out = (float*)d_out;

    float *p_bev_feat, *p_kv, *p_fused, *p_Q, *p_K, *p_V;
    cudaGetSymbolAddress((void**)&p_bev_feat, g_bev_feat);
    cudaGetSymbolAddress((void**)&p_kv, g_kv);
    cudaGetSymbolAddress((void**)&p_fused, g_fused);
    cudaGetSymbolAddress((void**)&p_Q, g_Q);
    cudaGetSymbolAddress((void**)&p_K, g_K);
    cudaGetSymbolAddress((void**)&p_V, g_V);

    const float scaleQ = 0.17677669529663687f * 1.4426950408889634f;

    ego_spread_kernel<<<512, 256>>>(ego);
    resize_front_kernel<<<2048, 256>>>(front);

    conv_mma_kernel<128, true><<<dim3(4, 4, 8), 256>>>(bev, w_bev, b_bev, p_bev_feat, 128);
    conv_mma_kernel<64, false><<<dim3(4, 4, 8), 256>>>(hd, w_hd, b_hd, p_kv, 192);

    proj_qkv_mma<<<dim3(8, 8), 256>>>(p_bev_feat, wq, p_Q, 128, scaleQ);
    proj_qkv_mma<<<dim3(8, 8), 256>>>(p_kv, wk, p_K, 192, 1.0f);
    proj_qkv_mma<<<dim3(8, 8), 256>>>(p_kv, wv, p_V, 192, 1.0f);

    attn_mma_kernel<<<dim3(8, 4, 8), 256>>>();

    proj_out_mma<<<dim3(8, 8), 256>>>(wo, bo);

    conv_mma_kernel<128, true><<<dim3(4, 4, 8), 256>>>(p_fused, w_out, b_out, out, 128);
}